// round 4
// baseline (speedup 1.0000x reference)
#include <cuda_runtime.h>

#define BB 32
#define CC 256
#define HWL 3136           // 56*56
#define HID 32
#define NPLANE (BB*CC)     // 8192

__device__ float g_pooled[NPLANE];

// ---------------------------------------------------------------------------
// Kernel 1: mean over H*W per (b,c) plane. ONE WARP per plane.
// Loads via __ldcg: cache in L2 (wanted for the apply pass), skip L1 fills.
// ---------------------------------------------------------------------------
__global__ __launch_bounds__(256) void pool_kernel(const float* __restrict__ x) {
    const int warp = (blockIdx.x << 3) | (threadIdx.x >> 5);  // plane id
    const int lane = threadIdx.x & 31;
    const float4* xp = reinterpret_cast<const float4*>(x + (size_t)warp * HWL);

    float s = 0.f;
    int i = lane;
#pragma unroll 12
    for (int it = 0; it < 24; it++, i += 32) {
        float4 v = __ldcg(&xp[i]);
        s += (v.x + v.y) + (v.z + v.w);
    }
    if (lane < 16) {
        float4 v = __ldcg(&xp[768 + lane]);
        s += (v.x + v.y) + (v.z + v.w);
    }
#pragma unroll
    for (int o = 16; o > 0; o >>= 1) s += __shfl_xor_sync(0xffffffffu, s, o);
    if (lane == 0) g_pooled[warp] = s * (1.0f / HWL);
}

// ---------------------------------------------------------------------------
// Kernel 2 (fused): per-CTA recompute of h[b] + per-warp coefficients +
// streaming apply. CTA = 8 planes (same batch b), grid = 1024.
// x loads: __ldcs (evict-first, no L1 fill; still hits the L2-resident copy).
// out stores: __stcs (evict-first; don't displace x in L2).
// ---------------------------------------------------------------------------
__global__ __launch_bounds__(256) void fused_apply_kernel(
        const float* __restrict__ x,
        const float* __restrict__ fc1_w,
        const float* __restrict__ fc1_b,
        const float* __restrict__ fc2_w,
        const float* __restrict__ fc2_b,
        float* __restrict__ out) {
    const int tid = threadIdx.x;
    const int b = blockIdx.x >> 5;                 // 32 CTAs per batch
    const int cbase = (blockIdx.x & 31) << 3;      // 8 channels per CTA

    __shared__ float p_s[CC];
    __shared__ float h_s[HID];

    p_s[tid] = g_pooled[b * CC + tid];
    __syncthreads();

    // h[j] = relu(fc1_w[j,:] . pooled[b,:] + fc1_b[j]); 256 thr = 32 j x 8 partials
    {
        const int j = tid >> 3;
        const int part = tid & 7;
        const float* wrow = fc1_w + j * CC + part * 32;
        const float* pp = p_s + part * 32;
        float acc = 0.f;
#pragma unroll
        for (int i2 = 0; i2 < 32; i2++) acc = fmaf(pp[i2], wrow[i2], acc);
#pragma unroll
        for (int o = 4; o > 0; o >>= 1) acc += __shfl_down_sync(0xffffffffu, acc, o, 8);
        if (part == 0) h_s[j] = fmaxf(acc + fc1_b[j], 0.f);
    }
    __syncthreads();

    const int warp = tid >> 5;
    const int lane = tid & 31;
    const int c = cbase + warp;
    const int plane = b * CC + c;

    // 4 coefficient dots (k=0/1, alpha/beta), redundant per lane (broadcast loads).
    const float* wa0 = fc2_w + (size_t)(2 * c) * HID;
    const float* wb0 = wa0 + HID;
    const float* wa1 = fc2_w + (size_t)(2 * CC + 2 * c) * HID;
    const float* wb1 = wa1 + HID;
    float da0 = fc2_b[2 * c];
    float db0 = fc2_b[2 * c + 1];
    float da1 = fc2_b[2 * CC + 2 * c];
    float db1 = fc2_b[2 * CC + 2 * c + 1];
#pragma unroll
    for (int j = 0; j < HID; j++) {
        float hj = h_s[j];
        da0 = fmaf(wa0[j], hj, da0);
        db0 = fmaf(wb0[j], hj, db0);
        da1 = fmaf(wa1[j], hj, da1);
        db1 = fmaf(wb1[j], hj, db1);
    }
    // 2*sigmoid(z)-1 == tanh(z/2); init_alpha/beta = 1 for k=0, 0 for k=1
    const float a0 = 1.0f + tanhf(0.5f * da0);            // LAMBDA_ALPHA = 1.0
    const float c0 = 1.0f + 0.5f * tanhf(0.5f * db0);     // LAMBDA_BETA  = 0.5
    const float a1 = tanhf(0.5f * da1);
    const float c1 = 0.5f * tanhf(0.5f * db1);

    const float4* xp = reinterpret_cast<const float4*>(x + (size_t)plane * HWL);
    float4* op = reinterpret_cast<float4*>(out + (size_t)plane * HWL);

    int i = lane;
#pragma unroll 12
    for (int it = 0; it < 24; it++, i += 32) {
        float4 v = __ldcs(&xp[i]);
        float4 r;
        r.x = fmaxf(fmaf(v.x, a0, c0), fmaf(v.x, a1, c1));
        r.y = fmaxf(fmaf(v.y, a0, c0), fmaf(v.y, a1, c1));
        r.z = fmaxf(fmaf(v.z, a0, c0), fmaf(v.z, a1, c1));
        r.w = fmaxf(fmaf(v.w, a0, c0), fmaf(v.w, a1, c1));
        __stcs(&op[i], r);
    }
    if (lane < 16) {
        float4 v = __ldcs(&xp[768 + lane]);
        float4 r;
        r.x = fmaxf(fmaf(v.x, a0, c0), fmaf(v.x, a1, c1));
        r.y = fmaxf(fmaf(v.y, a0, c0), fmaf(v.y, a1, c1));
        r.z = fmaxf(fmaf(v.z, a0, c0), fmaf(v.z, a1, c1));
        r.w = fmaxf(fmaf(v.w, a0, c0), fmaf(v.w, a1, c1));
        __stcs(&op[768 + lane], r);
    }
}

extern "C" void kernel_launch(void* const* d_in, const int* in_sizes, int n_in,
                              void* d_out, int out_size) {
    const float* x      = (const float*)d_in[0];
    const float* fc1_w  = (const float*)d_in[1];
    const float* fc1_b  = (const float*)d_in[2];
    const float* fc2_w  = (const float*)d_in[3];
    const float* fc2_b  = (const float*)d_in[4];
    float* out = (float*)d_out;

    pool_kernel<<<NPLANE / 8, 256>>>(x);
    fused_apply_kernel<<<NPLANE / 8, 256>>>(x, fc1_w, fc1_b, fc2_w, fc2_b, out);
}

// round 5
// speedup vs baseline: 1.0800x; 1.0800x over previous
#include <cuda_runtime.h>

#define BB 32
#define CC 256
#define HWL 3136           // 56*56
#define HID 32
#define NPLANE (BB*CC)     // 8192
#define PF 6               // prefetch depth (float4 ring)

__device__ float g_pooled[NPLANE];

// ---------------------------------------------------------------------------
// Kernel 1: mean over H*W per (b,c) plane. ONE WARP per plane. (R2-proven)
// ---------------------------------------------------------------------------
__global__ __launch_bounds__(256) void pool_kernel(const float* __restrict__ x) {
    const int warp = (blockIdx.x << 3) | (threadIdx.x >> 5);  // plane id
    const int lane = threadIdx.x & 31;
    const float4* xp = reinterpret_cast<const float4*>(x + (size_t)warp * HWL);

    float s = 0.f;
    int i = lane;
#pragma unroll 12
    for (int it = 0; it < 24; it++, i += 32) {
        float4 v = __ldg(&xp[i]);
        s += (v.x + v.y) + (v.z + v.w);
    }
    if (lane < 16) {
        float4 v = __ldg(&xp[768 + lane]);
        s += (v.x + v.y) + (v.z + v.w);
    }
#pragma unroll
    for (int o = 16; o > 0; o >>= 1) s += __shfl_xor_sync(0xffffffffu, s, o);
    if (lane == 0) g_pooled[warp] = s * (1.0f / HWL);
}

// ---------------------------------------------------------------------------
// Kernel 2 (fused): coefficients + apply. CTA = 8 planes (one batch b).
// Plain LDG/STG, 6-deep software pipeline, 64-reg budget.
// ---------------------------------------------------------------------------
__global__ __launch_bounds__(256, 4) void fused_apply_kernel(
        const float* __restrict__ x,
        const float* __restrict__ fc1_w,
        const float* __restrict__ fc1_b,
        const float* __restrict__ fc2_w,
        const float* __restrict__ fc2_b,
        float* __restrict__ out) {
    const int tid = threadIdx.x;
    const int b = blockIdx.x >> 5;                 // 32 CTAs per batch
    const int cbase = (blockIdx.x & 31) << 3;      // 8 channels per CTA

    __shared__ float p_s[CC];
    __shared__ float h_s[HID];

    p_s[tid] = g_pooled[b * CC + tid];
    __syncthreads();

    // h[j] = relu(fc1_w[j,:] . pooled[b,:] + fc1_b[j]); 32 j x 8 partials
    {
        const int j = tid >> 3;
        const int part = tid & 7;
        const float* wrow = fc1_w + j * CC + part * 32;
        const float* pp = p_s + part * 32;
        float acc = 0.f;
#pragma unroll
        for (int i2 = 0; i2 < 32; i2++) acc = fmaf(pp[i2], wrow[i2], acc);
#pragma unroll
        for (int o = 4; o > 0; o >>= 1) acc += __shfl_down_sync(0xffffffffu, acc, o, 8);
        if (part == 0) h_s[j] = fmaxf(acc + fc1_b[j], 0.f);
    }
    __syncthreads();

    const int warp = tid >> 5;
    const int lane = tid & 31;
    const int c = cbase + warp;
    const int plane = b * CC + c;

    // 4 coefficient dots (k=0/1, alpha/beta), redundant per lane.
    const float* wa0 = fc2_w + (size_t)(2 * c) * HID;
    const float* wb0 = wa0 + HID;
    const float* wa1 = fc2_w + (size_t)(2 * CC + 2 * c) * HID;
    const float* wb1 = wa1 + HID;
    float da0 = fc2_b[2 * c];
    float db0 = fc2_b[2 * c + 1];
    float da1 = fc2_b[2 * CC + 2 * c];
    float db1 = fc2_b[2 * CC + 2 * c + 1];
#pragma unroll
    for (int j = 0; j < HID; j++) {
        float hj = h_s[j];
        da0 = fmaf(wa0[j], hj, da0);
        db0 = fmaf(wb0[j], hj, db0);
        da1 = fmaf(wa1[j], hj, da1);
        db1 = fmaf(wb1[j], hj, db1);
    }
    // 2*sigmoid(z)-1 == tanh(z/2); init_alpha/beta = 1 for k=0, 0 for k=1
    const float a0 = 1.0f + tanhf(0.5f * da0);            // LAMBDA_ALPHA = 1.0
    const float c0 = 1.0f + 0.5f * tanhf(0.5f * db0);     // LAMBDA_BETA  = 0.5
    const float a1 = tanhf(0.5f * da1);
    const float c1 = 0.5f * tanhf(0.5f * db1);

    const float4* xp = reinterpret_cast<const float4*>(x + (size_t)plane * HWL);
    float4* op = reinterpret_cast<float4*>(out + (size_t)plane * HWL);

    // Software-pipelined main loop: 24 iters of 32 float4, PF=6 loads in flight.
    float4 buf[PF];
#pragma unroll
    for (int t = 0; t < PF; t++) buf[t] = xp[lane + 32 * t];

#pragma unroll
    for (int t = 0; t < 24; t++) {
        float4 v = buf[t % PF];
        if (t + PF < 24) buf[t % PF] = xp[lane + 32 * (t + PF)];
        float4 r;
        r.x = fmaxf(fmaf(v.x, a0, c0), fmaf(v.x, a1, c1));
        r.y = fmaxf(fmaf(v.y, a0, c0), fmaf(v.y, a1, c1));
        r.z = fmaxf(fmaf(v.z, a0, c0), fmaf(v.z, a1, c1));
        r.w = fmaxf(fmaf(v.w, a0, c0), fmaf(v.w, a1, c1));
        op[lane + 32 * t] = r;
    }
    // tail: 784 - 768 = 16 float4
    if (lane < 16) {
        float4 v = xp[768 + lane];
        float4 r;
        r.x = fmaxf(fmaf(v.x, a0, c0), fmaf(v.x, a1, c1));
        r.y = fmaxf(fmaf(v.y, a0, c0), fmaf(v.y, a1, c1));
        r.z = fmaxf(fmaf(v.z, a0, c0), fmaf(v.z, a1, c1));
        r.w = fmaxf(fmaf(v.w, a0, c0), fmaf(v.w, a1, c1));
        op[768 + lane] = r;
    }
}

extern "C" void kernel_launch(void* const* d_in, const int* in_sizes, int n_in,
                              void* d_out, int out_size) {
    const float* x      = (const float*)d_in[0];
    const float* fc1_w  = (const float*)d_in[1];
    const float* fc1_b  = (const float*)d_in[2];
    const float* fc2_w  = (const float*)d_in[3];
    const float* fc2_b  = (const float*)d_in[4];
    float* out = (float*)d_out;

    pool_kernel<<<NPLANE / 8, 256>>>(x);
    fused_apply_kernel<<<NPLANE / 8, 256>>>(x, fc1_w, fc1_b, fc2_w, fc2_b, out);
}

// round 6
// speedup vs baseline: 1.2021x; 1.1130x over previous
#include <cuda_runtime.h>
#include <cstdint>

#define BB 32
#define CC 256
#define HWL 3136           // 56*56
#define HW4 784            // HWL/4
#define HID 32
#define NPLANE (BB*CC)     // 8192
#define PLANE_BYTES (HWL * 4)   // 12544, multiple of 16

__device__ float g_pooled[NPLANE];
__device__ float g_a0[NPLANE];
__device__ float g_c0[NPLANE];
__device__ float g_a1[NPLANE];
__device__ float g_c1[NPLANE];

__device__ __forceinline__ uint32_t smem_u32(const void* p) {
    return (uint32_t)__cvta_generic_to_shared(p);
}

__device__ __forceinline__ void mbar_wait_parity0(uint32_t mbar) {
    asm volatile(
        "{\n\t"
        ".reg .pred P;\n\t"
        "W_%=:\n\t"
        "mbarrier.try_wait.parity.shared.b64 P, [%0], 0;\n\t"
        "@!P bra W_%=;\n\t"
        "}"
        :: "r"(mbar) : "memory");
}

// ---------------------------------------------------------------------------
// Kernel 1: mean over H*W per plane. ONE WARP per plane. (R2-proven, 19.8us)
// ---------------------------------------------------------------------------
__global__ __launch_bounds__(256) void pool_kernel(const float* __restrict__ x) {
    const int warp = (blockIdx.x << 3) | (threadIdx.x >> 5);
    const int lane = threadIdx.x & 31;
    const float4* xp = reinterpret_cast<const float4*>(x + (size_t)warp * HWL);

    float s = 0.f;
    int i = lane;
#pragma unroll 12
    for (int it = 0; it < 24; it++, i += 32) {
        float4 v = __ldg(&xp[i]);
        s += (v.x + v.y) + (v.z + v.w);
    }
    if (lane < 16) {
        float4 v = __ldg(&xp[768 + lane]);
        s += (v.x + v.y) + (v.z + v.w);
    }
#pragma unroll
    for (int o = 16; o > 0; o >>= 1) s += __shfl_xor_sync(0xffffffffu, s, o);
    if (lane == 0) g_pooled[warp] = s * (1.0f / HWL);
}

// ---------------------------------------------------------------------------
// Kernel 2: tiny MLP -> per-plane coefficient tables (4 x 32KB, L2-resident).
// Grid = B = 32 blocks, 256 threads, each block handles batch b, all 256 c.
// ---------------------------------------------------------------------------
__global__ __launch_bounds__(256) void coef_kernel(const float* __restrict__ fc1_w,
                                                   const float* __restrict__ fc1_b,
                                                   const float* __restrict__ fc2_w,
                                                   const float* __restrict__ fc2_b) {
    const int b = blockIdx.x;

    __shared__ float p_s[CC];
    __shared__ float h_s[HID];

    p_s[threadIdx.x] = g_pooled[b * CC + threadIdx.x];
    __syncthreads();

    // h[j] = relu(fc1_w[j,:] . pooled + fc1_b[j]); 32 j x 8 partials
    {
        const int j = threadIdx.x >> 3;
        const int part = threadIdx.x & 7;
        const float* wrow = fc1_w + j * CC + part * 32;
        const float* pp = p_s + part * 32;
        float acc = 0.f;
#pragma unroll
        for (int i2 = 0; i2 < 32; i2++) acc = fmaf(pp[i2], wrow[i2], acc);
#pragma unroll
        for (int o = 4; o > 0; o >>= 1) acc += __shfl_down_sync(0xffffffffu, acc, o, 8);
        if (part == 0) h_s[j] = fmaxf(acc + fc1_b[j], 0.f);
    }
    __syncthreads();

    const int c = threadIdx.x;
    const float* wa0 = fc2_w + (size_t)(2 * c) * HID;
    const float* wb0 = wa0 + HID;
    const float* wa1 = fc2_w + (size_t)(2 * CC + 2 * c) * HID;
    const float* wb1 = wa1 + HID;
    float da0 = fc2_b[2 * c];
    float db0 = fc2_b[2 * c + 1];
    float da1 = fc2_b[2 * CC + 2 * c];
    float db1 = fc2_b[2 * CC + 2 * c + 1];
#pragma unroll
    for (int j = 0; j < HID; j++) {
        float hj = h_s[j];
        da0 = fmaf(wa0[j], hj, da0);
        db0 = fmaf(wb0[j], hj, db0);
        da1 = fmaf(wa1[j], hj, da1);
        db1 = fmaf(wb1[j], hj, db1);
    }
    const int plane = b * CC + c;
    // 2*sigmoid(z)-1 == tanh(z/2); init = 1 for k=0, 0 for k=1
    g_a0[plane] = 1.0f + tanhf(0.5f * da0);          // LAMBDA_ALPHA = 1.0
    g_c0[plane] = 1.0f + 0.5f * tanhf(0.5f * db0);   // LAMBDA_BETA  = 0.5
    g_a1[plane] = tanhf(0.5f * da1);
    g_c1[plane] = 0.5f * tanhf(0.5f * db1);
}

// ---------------------------------------------------------------------------
// Kernel 3: TMA apply. One CTA per plane. Bulk-load plane -> SMEM, compute
// in place via LDS/STS, bulk-store SMEM -> out. GMEM never touches the
// per-instruction LDG/STG L1tex path.
// ---------------------------------------------------------------------------
__global__ __launch_bounds__(256) void apply_tma_kernel(const float* __restrict__ x,
                                                        float* __restrict__ out) {
    __shared__ alignas(16) float tile[HWL];
    __shared__ alignas(8) unsigned long long mbar;

    const int plane = blockIdx.x;
    const int tid = threadIdx.x;
    const uint32_t mbar_a = smem_u32(&mbar);
    const uint32_t tile_a = smem_u32(tile);

    if (tid == 0) {
        asm volatile("mbarrier.init.shared.b64 [%0], 1;" :: "r"(mbar_a) : "memory");
    }
    __syncthreads();
    if (tid == 0) {
        asm volatile("mbarrier.arrive.expect_tx.shared.b64 _, [%0], %1;"
                     :: "r"(mbar_a), "r"((uint32_t)PLANE_BYTES) : "memory");
        asm volatile(
            "cp.async.bulk.shared::cluster.global.mbarrier::complete_tx::bytes "
            "[%0], [%1], %2, [%3];"
            :: "r"(tile_a), "l"(x + (size_t)plane * HWL),
               "r"((uint32_t)PLANE_BYTES), "r"(mbar_a) : "memory");
    }

    // Coefficients (tiny L2-resident tables), overlapped with the TMA load.
    const float a0 = g_a0[plane];
    const float c0 = g_c0[plane];
    const float a1 = g_a1[plane];
    const float c1 = g_c1[plane];

    mbar_wait_parity0(mbar_a);

    float4* t4 = reinterpret_cast<float4*>(tile);
#pragma unroll
    for (int i = tid; i < HW4; i += 256) {
        float4 v = t4[i];
        float4 r;
        r.x = fmaxf(fmaf(v.x, a0, c0), fmaf(v.x, a1, c1));
        r.y = fmaxf(fmaf(v.y, a0, c0), fmaf(v.y, a1, c1));
        r.z = fmaxf(fmaf(v.z, a0, c0), fmaf(v.z, a1, c1));
        r.w = fmaxf(fmaf(v.w, a0, c0), fmaf(v.w, a1, c1));
        t4[i] = r;
    }
    __syncthreads();

    if (tid == 0) {
        asm volatile("fence.proxy.async.shared::cta;" ::: "memory");
        asm volatile(
            "cp.async.bulk.global.shared::cta.bulk_group [%0], [%1], %2;"
            :: "l"(out + (size_t)plane * HWL), "r"(tile_a),
               "r"((uint32_t)PLANE_BYTES) : "memory");
        asm volatile("cp.async.bulk.commit_group;" ::: "memory");
        asm volatile("cp.async.bulk.wait_group 0;" ::: "memory");
    }
}

extern "C" void kernel_launch(void* const* d_in, const int* in_sizes, int n_in,
                              void* d_out, int out_size) {
    const float* x      = (const float*)d_in[0];
    const float* fc1_w  = (const float*)d_in[1];
    const float* fc1_b  = (const float*)d_in[2];
    const float* fc2_w  = (const float*)d_in[3];
    const float* fc2_b  = (const float*)d_in[4];
    float* out = (float*)d_out;

    pool_kernel<<<NPLANE / 8, 256>>>(x);
    coef_kernel<<<BB, 256>>>(fc1_w, fc1_b, fc2_w, fc2_b);
    apply_tma_kernel<<<NPLANE, 256>>>(x, out);
}